// round 1
// baseline (speedup 1.0000x reference)
#include <cuda_runtime.h>
#include <math.h>

// Problem constants
#define BB   8
#define CC   256
#define LL   512
#define GG   32      // groups
#define HH   8       // heads
#define DH   32      // head dim
#define EE   1024    // experts
#define HIDD 32      // expert hidden
#define CAPX 4       // expert capacity
#define NTOK (BB*CC) // 2048 tokens for MoE

// ---------------- scratch (__device__ globals, no allocation) ----------------
__device__ float g_xe  [BB*CC*LL];
__device__ float g_t1  [BB*CC*LL];
__device__ float g_t2  [BB*CC*LL];
__device__ float g_t3  [BB*CC*LL];
__device__ float g_s1  [BB*CC*LL];
__device__ float g_xt  [BB*LL*CC];
__device__ float g_qkv [BB*LL*3*CC];
__device__ float g_o   [BB*LL*CC];
__device__ float g_attn[BB*CC*LL];
__device__ float g_x2  [BB*CC*LL];
__device__ float g_probs[NTOK*EE];
__device__ float g_rawsum[BB*EE];
__device__ float g_cntf [BB*EE];
__device__ float g_v1[NTOK];  __device__ int g_i1[NTOK];
__device__ float g_v2[NTOK];  __device__ int g_i2[NTOK];
__device__ float g_g1[NTOK];  __device__ float g_g2[NTOK];
__device__ float g_yfull[BB*2*CC*LL];

__device__ __forceinline__ float gelu_exact(float v) {
    return 0.5f * v * (1.0f + erff(v * 0.70710678118654752440f));
}

// ---------------- elementwise add ----------------
__global__ void add_kernel(const float* __restrict__ a, const float* __restrict__ b,
                           float* __restrict__ out, int n) {
    int i = blockIdx.x * blockDim.x + threadIdx.x;
    if (i < n) out[i] = a[i] + b[i];
}

// ---------------- fused GroupNorm + GELU ----------------
// one block per (b, g). Group data is contiguous: 8 channels * 512 = 4096 floats.
__global__ void gn_gelu_kernel(const float* __restrict__ in,
                               const float* __restrict__ scale,
                               const float* __restrict__ bias,
                               float* __restrict__ out) {
    int bg = blockIdx.x;
    int b = bg >> 5, g = bg & 31;
    const float* base = in  + ((size_t)b * CC + g * 8) * LL;
    float* obase      = out + ((size_t)b * CC + g * 8) * LL;
    __shared__ float rs[256], rq[256];
    int tid = threadIdx.x;
    float s = 0.f, q = 0.f;
    for (int i = tid; i < 4096; i += 256) { float v = base[i]; s += v; q += v * v; }
    rs[tid] = s; rq[tid] = q;
    __syncthreads();
    for (int st = 128; st > 0; st >>= 1) {
        if (tid < st) { rs[tid] += rs[tid + st]; rq[tid] += rq[tid + st]; }
        __syncthreads();
    }
    float mu  = rs[0] * (1.f / 4096.f);
    float var = rq[0] * (1.f / 4096.f) - mu * mu;
    float inv = rsqrtf(var + 1e-5f);
    for (int i = tid; i < 4096; i += 256) {
        int c = g * 8 + (i >> 9);
        float v = (base[i] - mu) * inv * scale[c] + bias[c];
        obase[i] = gelu_exact(v);
    }
}

// ---------------- direct conv1d, k=3, pad=1 ----------------
// grid (B, Cout/16, L/128), block 128. Each block: 16 out-channels x 128 positions.
__global__ void conv1d_kernel(const float* __restrict__ in,
                              const float* __restrict__ w,
                              const float* __restrict__ bias,
                              const float* __restrict__ residual,
                              float* __restrict__ out,
                              int Cin, int Cout) {
    int b = blockIdx.x;
    int co0 = blockIdx.y * 16;
    int l0 = blockIdx.z * 128;
    int tid = threadIdx.x;
    int l = l0 + tid;
    __shared__ float sIn[130];
    __shared__ float sW[48];
    float acc[16];
#pragma unroll
    for (int j = 0; j < 16; j++) acc[j] = 0.f;
    for (int ci = 0; ci < Cin; ci++) {
        __syncthreads();
        for (int i = tid; i < 130; i += 128) {
            int idx = l0 - 1 + i;
            sIn[i] = (idx >= 0 && idx < LL) ? in[((size_t)b * Cin + ci) * LL + idx] : 0.f;
        }
        if (tid < 48)
            sW[tid] = w[((size_t)(co0 + tid / 3)) * Cin * 3 + ci * 3 + (tid % 3)];
        __syncthreads();
        float x0 = sIn[tid], x1 = sIn[tid + 1], x2 = sIn[tid + 2];
#pragma unroll
        for (int j = 0; j < 16; j++)
            acc[j] += x0 * sW[j * 3 + 0] + x1 * sW[j * 3 + 1] + x2 * sW[j * 3 + 2];
    }
#pragma unroll
    for (int j = 0; j < 16; j++) {
        int co = co0 + j;
        float v = acc[j] + bias[co];
        size_t oi = ((size_t)b * Cout + co) * LL + l;
        if (residual) v += residual[oi];
        out[oi] = v;
    }
}

// ---------------- transpose (b,C,L) -> (b,L,C) ----------------
__global__ void transpose_kernel(const float* __restrict__ in, float* __restrict__ out) {
    __shared__ float tile[32][33];
    int b = blockIdx.z;
    int c0 = blockIdx.y * 32, l0 = blockIdx.x * 32;
    int tx = threadIdx.x, ty = threadIdx.y; // (32,8)
#pragma unroll
    for (int r = 0; r < 32; r += 8)
        tile[ty + r][tx] = in[((size_t)b * CC + c0 + ty + r) * LL + l0 + tx];
    __syncthreads();
#pragma unroll
    for (int r = 0; r < 32; r += 8)
        out[((size_t)b * LL + l0 + ty + r) * CC + c0 + tx] = tile[tx][ty + r];
}

// ---------------- tiled SGEMM: C = A(MxK) * B(KxN) + bias ----------------
// M,N multiples of 64; K multiple of 16.
// transOut==0 : C row-major MxN.
// transOut==1 : row = b*512 + l, write C[(b*N + col)*512 + l]  (token->channel-major)
__global__ void __launch_bounds__(256) sgemm_kernel(int M, int N, int K,
                                                    const float* __restrict__ A,
                                                    const float* __restrict__ Bm,
                                                    const float* __restrict__ bias,
                                                    float* __restrict__ Cm,
                                                    int transOut) {
    __shared__ float As[16][65];
    __shared__ float Bs[16][64];
    int tid = threadIdx.x;
    int tx = tid & 15, ty = tid >> 4;
    int rowBase = blockIdx.y * 64;
    int colBase = blockIdx.x * 64;
    float acc[4][4];
#pragma unroll
    for (int i = 0; i < 4; i++)
#pragma unroll
        for (int j = 0; j < 4; j++) acc[i][j] = 0.f;

    for (int k0 = 0; k0 < K; k0 += 16) {
#pragma unroll
        for (int i = 0; i < 4; i++) {
            int idx = tid + i * 256;
            int r = idx >> 4, kk = idx & 15;
            As[kk][r] = A[(size_t)(rowBase + r) * K + k0 + kk];
        }
#pragma unroll
        for (int i = 0; i < 4; i++) {
            int idx = tid + i * 256;
            int kk = idx >> 6, c = idx & 63;
            Bs[kk][c] = Bm[(size_t)(k0 + kk) * N + colBase + c];
        }
        __syncthreads();
#pragma unroll
        for (int kk = 0; kk < 16; kk++) {
            float a[4], bb[4];
#pragma unroll
            for (int i = 0; i < 4; i++) { a[i] = As[kk][ty * 4 + i]; bb[i] = Bs[kk][tx * 4 + i]; }
#pragma unroll
            for (int i = 0; i < 4; i++)
#pragma unroll
                for (int j = 0; j < 4; j++) acc[i][j] += a[i] * bb[j];
        }
        __syncthreads();
    }
#pragma unroll
    for (int i = 0; i < 4; i++) {
#pragma unroll
        for (int j = 0; j < 4; j++) {
            int row = rowBase + ty * 4 + i;
            int col = colBase + tx * 4 + j;
            float v = acc[i][j] + (bias ? bias[col] : 0.f);
            if (!transOut) {
                Cm[(size_t)row * N + col] = v;
            } else {
                int b = row >> 9, l = row & 511;
                Cm[((size_t)b * N + col) * LL + l] = v;
            }
        }
    }
}

// ---------------- attention core ----------------
// grid = B*H blocks, 256 threads. smem: K,V tiles 512x32 padded to 33.
__global__ void __launch_bounds__(256) attn_kernel(const float* __restrict__ qkv,
                                                   float* __restrict__ o) {
    extern __shared__ float sh[];
    float* Ks = sh;
    float* Vs = sh + 512 * 33;
    __shared__ float qrow[8][32];
    int bh = blockIdx.x;
    int b = bh >> 3, h = bh & 7;
    int tid = threadIdx.x;
    int warp = tid >> 5, lane = tid & 31;
    const float* base = qkv + (size_t)b * 512 * 768;
    for (int i = tid; i < 512 * 32; i += 256) {
        int j = i >> 5, d = i & 31;
        const float* p = base + (size_t)j * 768 + (d * 8 + h) * 3;
        Ks[j * 33 + d] = p[1];
        Vs[j * 33 + d] = p[2];
    }
    __syncthreads();
    const float scale = 0.1767766952966369f; // 1/sqrt(32)
    for (int r = warp; r < 512; r += 8) {
        qrow[warp][lane] = base[(size_t)r * 768 + (lane * 8 + h) * 3];
        __syncwarp();
        float s[16];
#pragma unroll
        for (int t = 0; t < 16; t++) {
            int j = t * 32 + lane;
            const float* kp = Ks + j * 33;
            float a = 0.f;
#pragma unroll
            for (int d = 0; d < 32; d++) a += qrow[warp][d] * kp[d];
            s[t] = a * scale;
        }
        float m = s[0];
#pragma unroll
        for (int t = 1; t < 16; t++) m = fmaxf(m, s[t]);
#pragma unroll
        for (int off = 16; off > 0; off >>= 1) m = fmaxf(m, __shfl_xor_sync(0xffffffffu, m, off));
        float sum = 0.f;
#pragma unroll
        for (int t = 0; t < 16; t++) { s[t] = expf(s[t] - m); sum += s[t]; }
#pragma unroll
        for (int off = 16; off > 0; off >>= 1) sum += __shfl_xor_sync(0xffffffffu, sum, off);
        float inv = 1.f / sum;
#pragma unroll
        for (int t = 0; t < 16; t++) s[t] *= inv;
        float accv = 0.f;
#pragma unroll
        for (int t = 0; t < 16; t++) {
#pragma unroll
            for (int src = 0; src < 32; src++) {
                float p = __shfl_sync(0xffffffffu, s[t], src);
                accv += p * Vs[(t * 32 + src) * 33 + lane];
            }
        }
        o[((size_t)(b * 512 + r)) * 256 + lane * 8 + h] = accv;
        __syncwarp();
    }
}

// ---------------- MoE: softmax over 1024 experts (in-place) ----------------
__global__ void softmax_kernel(float* __restrict__ logits) {
    int row = blockIdx.x;
    float* p = logits + (size_t)row * EE;
    __shared__ float red[256];
    int tid = threadIdx.x;
    float m = -1e30f;
    for (int e = tid; e < EE; e += 256) m = fmaxf(m, p[e]);
    red[tid] = m; __syncthreads();
    for (int st = 128; st > 0; st >>= 1) { if (tid < st) red[tid] = fmaxf(red[tid], red[tid + st]); __syncthreads(); }
    m = red[0]; __syncthreads();
    float s = 0.f;
    for (int e = tid; e < EE; e += 256) { float v = expf(p[e] - m); p[e] = v; s += v; }
    red[tid] = s; __syncthreads();
    for (int st = 128; st > 0; st >>= 1) { if (tid < st) red[tid] += red[tid + st]; __syncthreads(); }
    float inv = 1.f / red[0];
    for (int e = tid; e < EE; e += 256) p[e] *= inv;
}

// ---------------- top-2 with first-occurrence tie-break ----------------
__global__ void top2_kernel(const float* __restrict__ probs) {
    int row = blockIdx.x;
    const float* p = probs + (size_t)row * EE;
    __shared__ float sv[256]; __shared__ int si[256];
    int tid = threadIdx.x;
    float bv = -1e30f; int bi = 0;
    for (int e = tid * 4; e < tid * 4 + 4; e++) { float v = p[e]; if (v > bv) { bv = v; bi = e; } }
    sv[tid] = bv; si[tid] = bi; __syncthreads();
    for (int st = 128; st > 0; st >>= 1) {
        if (tid < st) {
            if (sv[tid + st] > sv[tid] || (sv[tid + st] == sv[tid] && si[tid + st] < si[tid])) {
                sv[tid] = sv[tid + st]; si[tid] = si[tid + st];
            }
        }
        __syncthreads();
    }
    float v1 = sv[0]; int i1 = si[0];
    __syncthreads();
    bv = -1e30f; bi = 0;
    for (int e = tid * 4; e < tid * 4 + 4; e++) {
        if (e == i1) continue;
        float v = p[e]; if (v > bv) { bv = v; bi = e; }
    }
    sv[tid] = bv; si[tid] = bi; __syncthreads();
    for (int st = 128; st > 0; st >>= 1) {
        if (tid < st) {
            if (sv[tid + st] > sv[tid] || (sv[tid + st] == sv[tid] && si[tid + st] < si[tid])) {
                sv[tid] = sv[tid + st]; si[tid] = si[tid + st];
            }
        }
        __syncthreads();
    }
    if (tid == 0) { g_v1[row] = v1; g_i1[row] = i1; g_v2[row] = sv[0]; g_i2[row] = si[0]; }
}

// ---------------- per-(b,e) sums of raw probs for aux loss ----------------
__global__ void colsum_kernel(const float* __restrict__ probs) {
    int b = blockIdx.x >> 2;
    int e = ((blockIdx.x & 3) << 8) + threadIdx.x;
    float s = 0.f;
    for (int n = 0; n < CC; n++) s += probs[((size_t)(b * CC + n)) * EE + e];
    g_rawsum[b * EE + e] = s;
}

// ---------------- sequential capacity routing per batch ----------------
__global__ void routing_kernel() {
    __shared__ int cnt1[EE];
    __shared__ int cnt2[EE];
    int b = blockIdx.x;
    int tid = threadIdx.x;
    for (int e = tid; e < EE; e += blockDim.x) { cnt1[e] = 0; cnt2[e] = 0; }
    __syncthreads();
    if (tid == 0) {
        for (int n = 0; n < CC; n++) {
            int t = b * CC + n;
            int e = g_i1[t];
            int pos = cnt1[e]++;
            float denom = g_v1[t] + g_v2[t] + 1e-9f;
            g_g1[t] = (pos < CAPX) ? (g_v1[t] / denom) : 0.f;
        }
        for (int n = 0; n < CC; n++) {
            int t = b * CC + n;
            int e = g_i2[t];
            int m1c = cnt1[e]; if (m1c > CAPX) m1c = CAPX;
            int pos = cnt2[e]++ + m1c;
            float denom = g_v1[t] + g_v2[t] + 1e-9f;
            g_g2[t] = (pos < CAPX) ? (g_v2[t] / denom) : 0.f;
        }
    }
    __syncthreads();
    for (int e = tid; e < EE; e += blockDim.x) g_cntf[b * EE + e] = (float)cnt1[e];
}

// ---------------- aux loss ----------------
__global__ void loss_kernel(float* __restrict__ out_aux) {
    __shared__ float red[256];
    int tid = threadIdx.x;
    float s = 0.f;
    for (int i = tid; i < BB * EE; i += 256) s += g_rawsum[i] * g_cntf[i];
    red[tid] = s; __syncthreads();
    for (int st = 128; st > 0; st >>= 1) { if (tid < st) red[tid] += red[tid + st]; __syncthreads(); }
    if (tid == 0) {
        float S = red[0];
        // mean_n raw = rawsum/256 ; mean_n m1 = cnt/256 ; mean over (b,e) ; * E^2 * 0.01
        float loss = (S / ((float)CC * (float)CC)) / ((float)BB * (float)EE)
                     * (float)EE * (float)EE * 0.01f;
        *out_aux = loss;
    }
}

// ---------------- per-token expert MLP (top-2) ----------------
__global__ void __launch_bounds__(128) moe_expert_kernel(const float* __restrict__ x,
                                                         const float* __restrict__ w1,
                                                         const float* __restrict__ w2,
                                                         float* __restrict__ out) {
    int t = blockIdx.x;
    __shared__ float xs[LL];
    __shared__ float red[128];
    __shared__ float hh[2][HIDD];
    int tid = threadIdx.x;
    const float* xr = x + (size_t)t * LL;
    for (int i = tid; i < LL; i += 128) xs[i] = xr[i];
    __syncthreads();
    int eArr[2] = { g_i1[t], g_i2[t] };
    float gArr[2] = { g_g1[t], g_g2[t] };
    for (int c = 0; c < 2; c++) {
        const float* W = w1 + (size_t)eArr[c] * LL * HIDD;
        int qv = tid >> 5, h = tid & 31;
        float part = 0.f;
        int d0 = qv * 128;
        for (int d = d0; d < d0 + 128; d++) part += xs[d] * W[d * 32 + h];
        red[tid] = part;
        __syncthreads();
        if (tid < 32) {
            float s = red[tid] + red[tid + 32] + red[tid + 64] + red[tid + 96];
            hh[c][tid] = gelu_exact(s);
        }
        __syncthreads();
    }
    const float* W2a = w2 + (size_t)eArr[0] * HIDD * LL;
    const float* W2b = w2 + (size_t)eArr[1] * HIDD * LL;
    for (int d = tid; d < LL; d += 128) {
        float a = 0.f, bv = 0.f;
#pragma unroll
        for (int h2 = 0; h2 < 32; h2++) {
            a  += hh[0][h2] * W2a[h2 * LL + d];
            bv += hh[1][h2] * W2b[h2 * LL + d];
        }
        out[(size_t)t * LL + d] = gArr[0] * a + gArr[1] * bv;
    }
}

// ---------------- maxpool: window 3, stride 2, pad 1 over L ----------------
__global__ void maxpool_kernel(const float* __restrict__ y, float* __restrict__ out) {
    int idx = blockIdx.x * blockDim.x + threadIdx.x;
    if (idx >= BB * 2 * CC * 256) return;
    int lp = idx & 255;
    int co = (idx >> 8) & 511;
    int b = idx >> 17;
    int l = lp * 2;
    float m = -INFINITY;
#pragma unroll
    for (int k = -1; k <= 1; k++) {
        int li = l + k;
        if (li >= 0 && li < LL) m = fmaxf(m, y[((size_t)b * 512 + co) * LL + li]);
    }
    out[idx] = m;
}

// ---------------- host orchestration ----------------
static float* sym(const void* symbol) {
    void* p = nullptr;
    cudaGetSymbolAddress(&p, symbol);
    return (float*)p;
}

extern "C" void kernel_launch(void* const* d_in, const int* in_sizes, int n_in,
                              void* d_out, int out_size) {
    const float* x_in   = (const float*)d_in[0];
    const float* emb    = (const float*)d_in[1];
    const float* rb1_g1s = (const float*)d_in[2];
    const float* rb1_g1b = (const float*)d_in[3];
    const float* rb1_c1w = (const float*)d_in[4];
    const float* rb1_c1b = (const float*)d_in[5];
    const float* rb1_g2s = (const float*)d_in[6];
    const float* rb1_g2b = (const float*)d_in[7];
    const float* rb1_c2w = (const float*)d_in[8];
    const float* rb1_c2b = (const float*)d_in[9];
    const float* rb2_g1s = (const float*)d_in[10];
    const float* rb2_g1b = (const float*)d_in[11];
    const float* rb2_c1w = (const float*)d_in[12];
    const float* rb2_c1b = (const float*)d_in[13];
    const float* rb2_g2s = (const float*)d_in[14];
    const float* rb2_g2b = (const float*)d_in[15];
    const float* rb2_c2w = (const float*)d_in[16];
    const float* rb2_c2b = (const float*)d_in[17];
    const float* attn_w1 = (const float*)d_in[18];
    const float* attn_b1 = (const float*)d_in[19];
    const float* attn_w2 = (const float*)d_in[20];
    const float* attn_b2 = (const float*)d_in[21];
    const float* moe_wg  = (const float*)d_in[22];
    const float* moe_w1  = (const float*)d_in[23];
    const float* moe_w2  = (const float*)d_in[24];
    const float* out_w   = (const float*)d_in[25];
    const float* out_b   = (const float*)d_in[26];

    float* out = (float*)d_out;
    const int Ysize = BB * 2 * CC * 256;          // 1048576
    float* y_out = out;
    float* x_out = out + Ysize;                   // MoE output (b,256,512)
    float* aux_out = out + (out_size - 1);

    float* p_xe   = sym(g_xe);
    float* p_t1   = sym(g_t1);
    float* p_t2   = sym(g_t2);
    float* p_t3   = sym(g_t3);
    float* p_s1   = sym(g_s1);
    float* p_xt   = sym(g_xt);
    float* p_qkv  = sym(g_qkv);
    float* p_o    = sym(g_o);
    float* p_attn = sym(g_attn);
    float* p_x2   = sym(g_x2);
    float* p_probs = sym(g_probs);
    float* p_yfull = sym(g_yfull);

    const int NEL = BB * CC * LL;

    // ---- res block 1 ----
    add_kernel<<<(NEL + 255) / 256, 256>>>(x_in, emb, p_xe, NEL);
    gn_gelu_kernel<<<BB * GG, 256>>>(p_xe, rb1_g1s, rb1_g1b, p_t1);
    conv1d_kernel<<<dim3(BB, 16, 4), 128>>>(p_t1, rb1_c1w, rb1_c1b, nullptr, p_t2, CC, CC);
    gn_gelu_kernel<<<BB * GG, 256>>>(p_t2, rb1_g2s, rb1_g2b, p_t3);
    conv1d_kernel<<<dim3(BB, 16, 4), 128>>>(p_t3, rb1_c2w, rb1_c2b, p_xe, p_s1, CC, CC);

    // ---- attention ----
    transpose_kernel<<<dim3(16, 8, BB), dim3(32, 8)>>>(p_s1, p_xt);
    sgemm_kernel<<<dim3(768 / 64, (BB * LL) / 64), 256>>>(BB * LL, 768, CC, p_xt, attn_w1, attn_b1, p_qkv, 0);
    size_t attn_smem = (size_t)2 * 512 * 33 * sizeof(float);
    cudaFuncSetAttribute(attn_kernel, cudaFuncAttributeMaxDynamicSharedMemorySize, (int)attn_smem);
    attn_kernel<<<BB * HH, 256, attn_smem>>>(p_qkv, p_o);
    sgemm_kernel<<<dim3(CC / 64, (BB * LL) / 64), 256>>>(BB * LL, CC, CC, p_o, attn_w2, attn_b2, p_attn, 1);

    // ---- res block 2 ----
    add_kernel<<<(NEL + 255) / 256, 256>>>(p_attn, emb, p_xe, NEL);
    gn_gelu_kernel<<<BB * GG, 256>>>(p_xe, rb2_g1s, rb2_g1b, p_t1);
    conv1d_kernel<<<dim3(BB, 16, 4), 128>>>(p_t1, rb2_c1w, rb2_c1b, nullptr, p_t2, CC, CC);
    gn_gelu_kernel<<<BB * GG, 256>>>(p_t2, rb2_g2s, rb2_g2b, p_t3);
    conv1d_kernel<<<dim3(BB, 16, 4), 128>>>(p_t3, rb2_c2w, rb2_c2b, p_xe, p_x2, CC, CC);

    // ---- MoE ----
    sgemm_kernel<<<dim3(EE / 64, NTOK / 64), 256>>>(NTOK, EE, LL, p_x2, moe_wg, nullptr, p_probs, 0);
    softmax_kernel<<<NTOK, 256>>>(p_probs);
    top2_kernel<<<NTOK, 256>>>(p_probs);
    colsum_kernel<<<BB * 4, 256>>>(p_probs);
    routing_kernel<<<BB, 256>>>();
    loss_kernel<<<1, 256>>>(aux_out);
    moe_expert_kernel<<<NTOK, 128>>>(p_x2, moe_w1, moe_w2, x_out);

    // ---- final conv + maxpool ----
    conv1d_kernel<<<dim3(BB, 32, 4), 128>>>(x_out, out_w, out_b, nullptr, p_yfull, CC, 2 * CC);
    maxpool_kernel<<<(Ysize + 255) / 256, 256>>>(p_yfull, y_out);
}

// round 10
// speedup vs baseline: 2.0291x; 2.0291x over previous
#include <cuda_runtime.h>
#include <math.h>
#include <stdint.h>

// Problem constants
#define BB   8
#define CC   256
#define LL   512
#define GG   32
#define HH   8
#define DH   32
#define EE   1024
#define HIDD 32
#define CAPX 4
#define NTOK (BB*CC)     // 2048 tokens
#define NBH  (BB*HH)     // 64 attention batches

// ---------------- scratch ----------------
__device__ float g_t1  [BB*CC*LL];
__device__ float g_t2  [BB*CC*LL];
__device__ float g_t3  [BB*CC*LL];
__device__ float g_s1  [BB*CC*LL];
__device__ float g_xt  [BB*LL*CC];
__device__ float g_qkv [BB*LL*3*CC];
__device__ float g_o   [BB*LL*CC];
__device__ float g_attn[BB*CC*LL];
__device__ float g_x2  [BB*CC*LL];
__device__ float g_col [768*4096];
__device__ float g_Qh  [NBH*512*32];
__device__ float g_Kt  [NBH*32*512];
__device__ float g_Vh  [NBH*512*64];
__device__ float g_Oh  [NBH*512*64];
__device__ float g_scores[NBH*512*512];
__device__ float g_probs[NTOK*EE];
__device__ float g_rawsum[BB*EE];
__device__ float g_cntf [BB*EE];
__device__ float g_v1[NTOK];  __device__ int g_i1[NTOK];
__device__ float g_v2[NTOK];  __device__ int g_i2[NTOK];
__device__ float g_g1[NTOK];  __device__ float g_g2[NTOK];
__device__ int   g_slot1[NTOK]; __device__ int g_slot2[NTOK];
__device__ int   g_ecount[EE];
__device__ int   g_etok[EE*32];
__device__ float g_eout[EE*32*512];
__device__ float g_yfull[BB*2*CC*LL];

__device__ __forceinline__ float gelu_exact(float v) {
    return 0.5f * v * (1.0f + erff(v * 0.70710678118654752440f));
}
__device__ __forceinline__ unsigned f2tf(float x) {
    unsigned r; asm("cvt.rna.tf32.f32 %0, %1;" : "=r"(r) : "f"(x)); return r;
}

// ---------------- fused (x [+ emb]) -> GroupNorm -> GELU ----------------
__global__ void gn_gelu_add(const float* __restrict__ in,
                            const float* __restrict__ in2,
                            const float* __restrict__ scale,
                            const float* __restrict__ bias,
                            float* __restrict__ out) {
    int bg = blockIdx.x;
    int b = bg >> 5, g = bg & 31;
    size_t off = ((size_t)b * CC + g * 8) * LL;
    const float4* base  = (const float4*)(in + off);
    const float4* base2 = in2 ? (const float4*)(in2 + off) : nullptr;
    float4* obase = (float4*)(out + off);
    __shared__ float rs[256], rq[256];
    int tid = threadIdx.x;
    float4 v[4];
    float s = 0.f, q = 0.f;
#pragma unroll
    for (int i = 0; i < 4; i++) {
        int idx = i * 256 + tid;
        float4 a = base[idx];
        if (base2) { float4 e = base2[idx]; a.x += e.x; a.y += e.y; a.z += e.z; a.w += e.w; }
        v[i] = a;
        s += a.x + a.y + a.z + a.w;
        q += a.x * a.x + a.y * a.y + a.z * a.z + a.w * a.w;
    }
    rs[tid] = s; rq[tid] = q;
    __syncthreads();
    for (int st = 128; st > 0; st >>= 1) {
        if (tid < st) { rs[tid] += rs[tid + st]; rq[tid] += rq[tid + st]; }
        __syncthreads();
    }
    float mu  = rs[0] * (1.f / 4096.f);
    float var = rq[0] * (1.f / 4096.f) - mu * mu;
    float inv = rsqrtf(var + 1e-5f);
#pragma unroll
    for (int i = 0; i < 4; i++) {
        int idx = i * 256 + tid;
        int c = g * 8 + (idx >> 7);
        float sc = scale[c] * inv, bi = bias[c] - mu * sc;
        float4 a = v[i];
        a.x = gelu_exact(a.x * sc + bi);
        a.y = gelu_exact(a.y * sc + bi);
        a.z = gelu_exact(a.z * sc + bi);
        a.w = gelu_exact(a.w * sc + bi);
        obase[idx] = a;
    }
}

// ---------------- im2col for k=3 pad=1 conv (Cin=256) ----------------
__global__ void im2col_kernel(const float* __restrict__ in, float* __restrict__ col) {
    int idx = blockIdx.x * blockDim.x + threadIdx.x;
    if (idx >= 768 * 4096) return;
    int row = idx >> 12;
    int c4  = idx & 4095;
    int ci = row / 3, k = row % 3;
    int b = c4 >> 9, l = c4 & 511;
    int li = l + k - 1;
    float v = (li >= 0 && li < LL) ? in[((size_t)b * CC + ci) * LL + li] : 0.f;
    col[idx] = v;
}

// ---------------- tf32x3 tensor-core GEMM (near-fp32 via hi/lo split) ----------------
// C(MxN) = alpha * A(MxK) @ B(KxN) + bias + residuals. M%64==0, N%64==0, K%32==0.
// mode 0: C[z*sC + row*N + col]            bias[col]
// mode 1: conv: b=col>>9,l=col&511 -> C[(b*M+row)*512+l], bias[row], +res1,res2 same idx
// mode 2: tok2ch: b=row>>9,l=row&511 -> C[(b*N+col)*512+l], bias[col]
__global__ void __launch_bounds__(128) gemm_tf32(
    int M, int N, int K,
    const float* __restrict__ A, const float* __restrict__ B,
    const float* __restrict__ bias,
    const float* __restrict__ res1, const float* __restrict__ res2,
    float* __restrict__ C,
    long long sA, long long sB, long long sC,
    float alpha, int mode)
{
    __shared__ unsigned Ah[32 * 73];
    __shared__ unsigned Al[32 * 73];
    __shared__ unsigned Bh[32 * 72];
    __shared__ unsigned Bl[32 * 72];
    int tid = threadIdx.x;
    int z = blockIdx.z;
    const float* Ab = A + (size_t)z * sA;
    const float* Bb = B + (size_t)z * sB;
    int rowBase = blockIdx.y * 64;
    int colBase = blockIdx.x * 64;

    int lane = tid & 31, warp = tid >> 5;
    int wm = (warp & 1) * 32, wn = (warp >> 1) * 32;
    int grp = lane >> 2, tg = lane & 3;

    float acc[2][4][4];
#pragma unroll
    for (int mi = 0; mi < 2; mi++)
#pragma unroll
        for (int ni = 0; ni < 4; ni++)
#pragma unroll
            for (int r = 0; r < 4; r++) acc[mi][ni][r] = 0.f;

    int af = tid & 7, ar = tid >> 3;    // A: float4 along K, 16 rows/iter
    int bc = tid & 15, bk = tid >> 4;   // B: float4 along N, 8 k-rows/iter

    for (int kb = 0; kb < K; kb += 32) {
#pragma unroll
        for (int i = 0; i < 4; i++) {
            int row = ar + i * 16;
            float4 v = *(const float4*)(Ab + (size_t)(rowBase + row) * K + kb + af * 4);
            float f[4] = { v.x, v.y, v.z, v.w };
#pragma unroll
            for (int c = 0; c < 4; c++) {
                unsigned h = f2tf(f[c]);
                Ah[(af * 4 + c) * 73 + row] = h;
                Al[(af * 4 + c) * 73 + row] = f2tf(f[c] - __uint_as_float(h));
            }
        }
#pragma unroll
        for (int i = 0; i < 4; i++) {
            int k = bk + i * 8;
            float4 v = *(const float4*)(Bb + (size_t)(kb + k) * N + colBase + bc * 4);
            float f[4] = { v.x, v.y, v.z, v.w };
#pragma unroll
            for (int c = 0; c < 4; c++) {
                unsigned h = f2tf(f[c]);
                Bh[k * 72 + bc * 4 + c] = h;
                Bl[k * 72 + bc * 4 + c] = f2tf(f[c] - __uint_as_float(h));
            }
        }
        __syncthreads();
#pragma unroll
        for (int ks = 0; ks < 4; ks++) {
            int k0 = ks * 8;
            unsigned ah[2][4], al[2][4], bh[4][2], bl[4][2];
#pragma unroll
            for (int mi = 0; mi < 2; mi++) {
                int m = wm + mi * 16 + grp;
                ah[mi][0] = Ah[(k0 + tg) * 73 + m];
                ah[mi][1] = Ah[(k0 + tg) * 73 + m + 8];
                ah[mi][2] = Ah[(k0 + tg + 4) * 73 + m];
                ah[mi][3] = Ah[(k0 + tg + 4) * 73 + m + 8];
                al[mi][0] = Al[(k0 + tg) * 73 + m];
                al[mi][1] = Al[(k0 + tg) * 73 + m + 8];
                al[mi][2] = Al[(k0 + tg + 4) * 73 + m];
                al[mi][3] = Al[(k0 + tg + 4) * 73 + m + 8];
            }
#pragma unroll
            for (int ni = 0; ni < 4; ni++) {
                int n = wn + ni * 8 + grp;
                bh[ni][0] = Bh[(k0 + tg) * 72 + n];
                bh[ni][1] = Bh[(k0 + tg + 4) * 72 + n];
                bl[ni][0] = Bl[(k0 + tg) * 72 + n];
                bl[ni][1] = Bl[(k0 + tg + 4) * 72 + n];
            }
#pragma unroll
            for (int mi = 0; mi < 2; mi++)
#pragma unroll
                for (int ni = 0; ni < 4; ni++) {
                    float* d = acc[mi][ni];
                    // hi*lo + lo*hi corrections first, hi*hi last
                    asm volatile(
                        "mma.sync.aligned.m16n8k8.row.col.f32.tf32.tf32.f32 "
                        "{%0,%1,%2,%3},{%4,%5,%6,%7},{%8,%9},{%0,%1,%2,%3};"
                        : "+f"(d[0]), "+f"(d[1]), "+f"(d[2]), "+f"(d[3])
                        : "r"(ah[mi][0]), "r"(ah[mi][1]), "r"(ah[mi][2]), "r"(ah[mi][3]),
                          "r"(bl[ni][0]), "r"(bl[ni][1]));
                    asm volatile(
                        "mma.sync.aligned.m16n8k8.row.col.f32.tf32.tf32.f32 "
                        "{%0,%1,%2,%3},{%4,%5,%6,%7},{%8,%9},{%0,%1,%2,%3};"
                        : "+f"(d[0]), "+f"(d[1]), "+f"(d[2]), "+f"(d[3])
                        : "r"(al[mi][0]), "r"(al[mi][1]), "r"(al[mi][2]), "r"(al[mi][3]),
                          "r"(bh[ni][0]), "r"(bh[ni][1]));
                    asm volatile(
                        "mma.sync.aligned.m16n8k8.row.col.f32.tf32.tf32.f32 "
                        "{%0,%1,%2,%3},{%4,%5,%6,%7},{%8,%9},{%0,%1,%2,%3};"
                        : "+f"(d[0]), "+f"(d[1]), "+f"(d[2]), "+f"(d[3])
                        : "r"(ah[mi][0]), "r"(ah[mi][1]), "r"(ah[mi][2]), "r"(ah[mi][3]),
                          "r"(bh[ni][0]), "r"(bh[ni][1]));
                }
        }
        __syncthreads();
    }

    float* Cb = C + (size_t)z * sC;
#pragma unroll
    for (int mi = 0; mi < 2; mi++) {
#pragma unroll
        for (int ni = 0; ni < 4; ni++) {
#pragma unroll
            for (int r = 0; r < 4; r++) {
                int row = rowBase + wm + mi * 16 + grp + ((r >= 2) ? 8 : 0);
                int col = colBase + wn + ni * 8 + tg * 2 + (r & 1);
                float v = acc[mi][ni][r] * alpha;
                if (mode == 0) {
                    if (bias) v += bias[col];
                    Cb[(size_t)row * N + col] = v;
                } else if (mode == 1) {
                    int b = col >> 9, l = col & 511;
                    size_t oi = ((size_t)b * M + row) * LL + l;
                    if (bias) v += bias[row];
                    if (res1) v += res1[oi];
                    if (res2) v += res2[oi];
                    Cb[oi] = v;
                } else {
                    int b = row >> 9, l = row & 511;
                    size_t oi = ((size_t)b * N + col) * LL + l;
                    if (bias) v += bias[col];
                    Cb[oi] = v;
                }
            }
        }
    }
}

// ---------------- transpose (b,C,L) -> (b*L, C) ----------------
__global__ void transpose_kernel(const float* __restrict__ in, float* __restrict__ out) {
    __shared__ float tile[32][33];
    int b = blockIdx.z;
    int c0 = blockIdx.y * 32, l0 = blockIdx.x * 32;
    int tx = threadIdx.x, ty = threadIdx.y;
#pragma unroll
    for (int r = 0; r < 32; r += 8)
        tile[ty + r][tx] = in[((size_t)b * CC + c0 + ty + r) * LL + l0 + tx];
    __syncthreads();
#pragma unroll
    for (int r = 0; r < 32; r += 8)
        out[((size_t)b * LL + l0 + ty + r) * CC + c0 + tx] = tile[tx][ty + r];
}

// ---------------- qkv split: (b,l,768) -> Qh[bh][l][d], Kt[bh][d][l], Vh[bh][l][64] ----------------
__global__ void qkv_split_kernel(const float* __restrict__ qkv) {
    int i = blockIdx.x * blockDim.x + threadIdx.x;
    if (i < NBH * 512 * 32) {
        int d = i & 31, l = (i >> 5) & 511, bh = i >> 14;
        int b = bh >> 3, h = bh & 7;
        const float* src = qkv + ((size_t)(b * 512 + l) * 768) + (d * 8 + h) * 3;
        g_Qh[(size_t)bh * 16384 + l * 32 + d] = src[0];
        g_Vh[(size_t)bh * 32768 + l * 64 + d] = src[2];
        g_Vh[(size_t)bh * 32768 + l * 64 + 32 + d] = 0.f;
        int l2 = i & 511, d2 = (i >> 9) & 31, bh2 = i >> 14;
        int b2 = bh2 >> 3, h2 = bh2 & 7;
        g_Kt[(size_t)bh2 * 16384 + d2 * 512 + l2] =
            qkv[((size_t)(b2 * 512 + l2) * 768) + (d2 * 8 + h2) * 3 + 1];
    }
}

// ---------------- generic row softmax (warp per row) ----------------
__global__ void softmax_rows(float* __restrict__ p, int cols) {
    int row = blockIdx.x * 8 + (threadIdx.x >> 5);
    int lane = threadIdx.x & 31;
    float4* r = (float4*)(p + (size_t)row * cols);
    int per = cols >> 7;
    float4 v[8];
    float m = -1e30f;
    for (int i = 0; i < per; i++) {
        v[i] = r[i * 32 + lane];
        m = fmaxf(m, fmaxf(fmaxf(v[i].x, v[i].y), fmaxf(v[i].z, v[i].w)));
    }
#pragma unroll
    for (int off = 16; off > 0; off >>= 1) m = fmaxf(m, __shfl_xor_sync(0xffffffffu, m, off));
    float s = 0.f;
    for (int i = 0; i < per; i++) {
        v[i].x = expf(v[i].x - m); v[i].y = expf(v[i].y - m);
        v[i].z = expf(v[i].z - m); v[i].w = expf(v[i].w - m);
        s += v[i].x + v[i].y + v[i].z + v[i].w;
    }
#pragma unroll
    for (int off = 16; off > 0; off >>= 1) s += __shfl_xor_sync(0xffffffffu, s, off);
    float inv = 1.f / s;
    for (int i = 0; i < per; i++) {
        v[i].x *= inv; v[i].y *= inv; v[i].z *= inv; v[i].w *= inv;
        r[i * 32 + lane] = v[i];
    }
}

// ---------------- merge heads: Oh[bh][l][64] -> g_o[(b*512+l)*256 + d*8+h] ----------------
__global__ void o_merge_kernel(float* __restrict__ o) {
    int i = blockIdx.x * blockDim.x + threadIdx.x;
    if (i >= BB * 512 * 256) return;
    int c = i & 255, l = (i >> 8) & 511, b = i >> 17;
    int h = c & 7, d = c >> 3;
    o[i] = g_Oh[(size_t)(b * 8 + h) * 32768 + l * 64 + d];
}

// ---------------- top-2 (first-occurrence tie-break) ----------------
__global__ void top2_kernel(const float* __restrict__ probs) {
    int row = blockIdx.x;
    const float* p = probs + (size_t)row * EE;
    __shared__ float sv[256]; __shared__ int si[256];
    int tid = threadIdx.x;
    float bv = -1e30f; int bi = 0;
    for (int e = tid * 4; e < tid * 4 + 4; e++) { float v = p[e]; if (v > bv) { bv = v; bi = e; } }
    sv[tid] = bv; si[tid] = bi; __syncthreads();
    for (int st = 128; st > 0; st >>= 1) {
        if (tid < st) {
            if (sv[tid + st] > sv[tid] || (sv[tid + st] == sv[tid] && si[tid + st] < si[tid])) {
                sv[tid] = sv[tid + st]; si[tid] = si[tid + st];
            }
        }
        __syncthreads();
    }
    float v1 = sv[0]; int i1 = si[0];
    __syncthreads();
    bv = -1e30f; bi = 0;
    for (int e = tid * 4; e < tid * 4 + 4; e++) {
        if (e == i1) continue;
        float v = p[e]; if (v > bv) { bv = v; bi = e; }
    }
    sv[tid] = bv; si[tid] = bi; __syncthreads();
    for (int st = 128; st > 0; st >>= 1) {
        if (tid < st) {
            if (sv[tid + st] > sv[tid] || (sv[tid + st] == sv[tid] && si[tid + st] < si[tid])) {
                sv[tid] = sv[tid + st]; si[tid] = si[tid + st];
            }
        }
        __syncthreads();
    }
    if (tid == 0) { g_v1[row] = v1; g_i1[row] = i1; g_v2[row] = sv[0]; g_i2[row] = si[0]; }
}

// ---------------- per-(b,e) raw prob sums for aux loss ----------------
__global__ void colsum_kernel(const float* __restrict__ probs) {
    int b = blockIdx.x >> 2;
    int e = ((blockIdx.x & 3) << 8) + threadIdx.x;
    float s = 0.f;
    for (int n = 0; n < CC; n++) s += probs[((size_t)(b * CC + n)) * EE + e];
    g_rawsum[b * EE + e] = s;
}

// ---------------- parallel capacity routing (one block per batch) ----------------
__global__ void routing_par() {
    __shared__ int si1[256], si2[256];
    __shared__ int scnt[EE];
    int b = blockIdx.x;
    int tid = threadIdx.x;
    int t = b * 256 + tid;
    si1[tid] = g_i1[t]; si2[tid] = g_i2[t];
    for (int e = tid; e < EE; e += 256) scnt[e] = 0;
    __syncthreads();
    atomicAdd(&scnt[si1[tid]], 1);
    int e1 = si1[tid], e2 = si2[tid];
    int pos1 = 0, cnt_e2 = 0;
    for (int m = 0; m < 256; m++) {
        int v = si1[m];
        pos1   += (v == e1 && m < tid);
        cnt_e2 += (v == e2);
    }
    float v1 = g_v1[t], v2 = g_v2[t];
    float denom = v1 + v2 + 1e-9f;
    float g1 = (pos1 < CAPX) ? (v1 / denom) : 0.f;
    int pos2 = min(cnt_e2, CAPX);
    for (int m = 0; m < 256; m++) {
        pos2 += (si2[m] == e2 && m < tid);
    }
    float g2 = (pos2 < CAPX) ? (v2 / denom) : 0.f;
    g_g1[t] = g1; g_g2[t] = g2;
    int s1 = 0, s2 = 0;
    if (g1 > 0.f) { s1 = atomicAdd(&g_ecount[e1], 1); g_etok[e1 * 32 + s1] = t; }
    if (g2 > 0.f) { s2 = atomicAdd(&g_ecount[e2], 1); g_etok[e2 * 32 + s2] = t; }
    g_slot1[t] = s1; g_slot2[t] = s2;
    __syncthreads();
    for (int e = tid; e < EE; e += 256) g_cntf[b * EE + e] = (float)scnt[e];
}

// ---------------- aux loss ----------------
__global__ void loss_kernel(float* __restrict__ out_aux) {
    __shared__ float red[256];
    int tid = threadIdx.x;
    float s = 0.f;
    for (int i = tid; i < BB * EE; i += 256) s += g_rawsum[i] * g_cntf[i];
    red[tid] = s; __syncthreads();
    for (int st = 128; st > 0; st >>= 1) { if (tid < st) red[tid] += red[tid + st]; __syncthreads(); }
    if (tid == 0) {
        float S = red[0];
        float loss = (S / ((float)CC * (float)CC)) / ((float)BB * (float)EE)
                     * (float)EE * (float)EE * 0.01f;
        *out_aux = loss;
    }
}

// ---------------- expert MLP, one block per expert, weights staged in smem ----------------
__global__ void __launch_bounds__(256) expert_kernel(const float* __restrict__ x,
                                                     const float* __restrict__ w1,
                                                     const float* __restrict__ w2) {
    int e = blockIdx.x;
    int cnt = g_ecount[e];
    if (cnt == 0) return;
    extern __shared__ float sm[];
    float* W1s = sm;             // [512][33]
    float* W2s = sm + 512 * 33;  // [32][512]
    float* hs  = W2s + 32 * 512; // [32 tok][32]
    int tid = threadIdx.x;
    const float* w1e = w1 + (size_t)e * 512 * 32;
    const float* w2e = w2 + (size_t)e * 32 * 512;
    for (int i = tid; i < 512 * 32; i += 256) {
        W1s[(i >> 5) * 33 + (i & 31)] = w1e[i];
        W2s[i] = w2e[i];
    }
    __syncthreads();
    int warp = tid >> 5, lane = tid & 31;
    for (int t0 = warp; t0 < cnt; t0 += 8) {
        int tok = g_etok[e * 32 + t0];
        const float* xr = x + (size_t)tok * 512;
        float xv[16];
#pragma unroll
        for (int i = 0; i < 16; i++) xv[i] = xr[lane + 32 * i];
#pragma unroll
        for (int j = 0; j < 32; j++) {
            float s = 0.f;
#pragma unroll
            for (int i = 0; i < 16; i++) s += xv[i] * W1s[(lane + 32 * i) * 33 + j];
#pragma unroll
            for (int off = 16; off > 0; off >>= 1) s += __shfl_xor_sync(0xffffffffu, s, off);
            if (lane == 0) hs[t0 * 32 + j] = gelu_exact(s);
        }
        __syncwarp();
        float hv[32];
#pragma unroll
        for (int j = 0; j < 32; j++) hv[j] = hs[t0 * 32 + j];
#pragma unroll
        for (int i = 0; i < 16; i++) {
            int d = lane + 32 * i;
            float s = 0.f;
#pragma unroll
            for (int j = 0; j < 32; j++) s += hv[j] * W2s[j * 512 + d];
            g_eout[((size_t)e * 32 + t0) * 512 + d] = s;
        }
    }
}

// ---------------- combine expert outputs per token ----------------
__global__ void combine_kernel(float* __restrict__ out) {
    int t = blockIdx.x;
    int tid = threadIdx.x;
    float g1 = g_g1[t], g2 = g_g2[t];
    float4 v = make_float4(0.f, 0.f, 0.f, 0.f);
    if (g1 > 0.f) {
        const float4* p = (const float4*)(g_eout + ((size_t)g_i1[t] * 32 + g_slot1[t]) * 512);
        float4 a = p[tid];
        v.x += g1 * a.x; v.y += g1 * a.y; v.z += g1 * a.z; v.w += g1 * a.w;
    }
    if (g2 > 0.f) {
        const float4* p = (const float4*)(g_eout + ((size_t)g_i2[t] * 32 + g_slot2[t]) * 512);
        float4 a = p[tid];
        v.x += g2 * a.x; v.y += g2 * a.y; v.z += g2 * a.z; v.w += g2 * a.w;
    }
    ((float4*)(out + (size_t)t * 512))[tid] = v;
}

// ---------------- maxpool w=3 s=2 p=1 ----------------
__global__ void maxpool_kernel(const float* __restrict__ y, float* __restrict__ out) {
    int idx = blockIdx.x * blockDim.x + threadIdx.x;
    if (idx >= BB * 2 * CC * 256) return;
    int lp = idx & 255;
    int co = (idx >> 8) & 511;
    int b = idx >> 17;
    int l = lp * 2;
    float m = -INFINITY;
#pragma unroll
    for (int k = -1; k <= 1; k++) {
        int li = l + k;
        if (li >= 0 && li < LL) m = fmaxf(m, y[((size_t)b * 512 + co) * LL + li]);
    }
    out[idx] = m;
}

// ---------------- host ----------------
static float* sym(const void* s) { void* p = nullptr; cudaGetSymbolAddress(&p, s); return (float*)p; }

extern "C" void kernel_launch(void* const* d_in, const int* in_sizes, int n_in,
                              void* d_out, int out_size) {
    const float* x_in   = (const float*)d_in[0];
    const float* emb    = (const float*)d_in[1];
    const float* rb1_g1s = (const float*)d_in[2];
    const float* rb1_g1b = (const float*)d_in[3];
    const float* rb1_c1w = (const float*)d_in[4];
    const float* rb1_c1b = (const float*)d_in[5];
    const float* rb1_g2s = (const float*)d_in[6];
    const float* rb1_g2b = (const float*)d_in[7];
    const float* rb1_c2w = (const float*)d_in[8];
    const float* rb1_c2b = (const float*)d_in[9];
    const float* rb2_g1s = (const float*)d_in[10];
    const float* rb2_g1b = (const float*)d_in[11];
    const float* rb2_c1w = (const float*)d_in[12];
    const float* rb2_c1b = (const float*)d_in[13];
    const float* rb2_g2s = (const float*)d_in[14];
    const float* rb2_g2b = (const float*)d_in[15];
    const float* rb2_c2w = (const float*)d_in[16];
    const float* rb2_c2b = (const float*)d_in[17];
    const float* attn_w1 = (const float*)d_in[18];
    const float* attn_b1 = (const float*)d_in[19];
    const float* attn_w2 = (const float*)d_in[20];
    const float* attn_b2 = (const float*)d_in[21];
    const float* moe_wg  = (const float*)d_in[22];
    const float* moe_w1  = (const float*)d_in[23];
    const float* moe_w2  = (const float*)d_in[24];
    const float* out_w   = (const float*)d_in[25];
    const float* out_b   = (const float*)d_in[26];

    float* out = (float*)d_out;
    const int Ysize = BB * 2 * CC * 256;
    float* y_out = out;
    float* x_out = out + Ysize;
    float* aux_out = out + (out_size - 1);

    float* p_t1 = sym(g_t1); float* p_t2 = sym(g_t2); float* p_t3 = sym(g_t3);
    float* p_s1 = sym(g_s1); float* p_xt = sym(g_xt); float* p_qkv = sym(g_qkv);
    float* p_o = sym(g_o);  float* p_attn = sym(g_attn); float* p_x2 = sym(g_x2);
    float* p_col = sym(g_col); float* p_probs = sym(g_probs); float* p_yfull = sym(g_yfull);
    float* p_Qh = sym(g_Qh); float* p_Kt = sym(g_Kt); float* p_Vh = sym(g_Vh);
    float* p_Oh = sym(g_Oh); float* p_sc = sym(g_scores);
    void* p_ecount = nullptr; cudaGetSymbolAddress(&p_ecount, g_ecount);

    const int expert_smem = (512 * 33 + 32 * 512 + 32 * 32) * 4;
    cudaFuncSetAttribute(expert_kernel, cudaFuncAttributeMaxDynamicSharedMemorySize, expert_smem);

    const float ascale = 0.17677669529663687f;  // 1/sqrt(32)

    // ---- res block 1 ----
    gn_gelu_add<<<BB * GG, 256>>>(x_in, emb, rb1_g1s, rb1_g1b, p_t1);
    im2col_kernel<<<(768 * 4096) / 256, 256>>>(p_t1, p_col);
    gemm_tf32<<<dim3(64, 4, 1), 128>>>(256, 4096, 768, rb1_c1w, p_col, rb1_c1b,
                                       nullptr, nullptr, p_t2, 0, 0, 0, 1.f, 1);
    gn_gelu_add<<<BB * GG, 256>>>(p_t2, nullptr, rb1_g2s, rb1_g2b, p_t3);
    im2col_kernel<<<(768 * 4096) / 256, 256>>>(p_t3, p_col);
    gemm_tf32<<<dim3(64, 4, 1), 128>>>(256, 4096, 768, rb1_c2w, p_col, rb1_c2b,
                                       x_in, emb, p_s1, 0, 0, 0, 1.f, 1);

    // ---- attention ----
    transpose_kernel<<<dim3(16, 8, BB), dim3(32, 8)>>>(p_s1, p_xt);
    gemm_tf32<<<dim3(12, 64, 1), 128>>>(4096, 768, 256, p_xt, attn_w1, attn_b1,
                                        nullptr, nullptr, p_qkv, 0, 0, 0, 1.f, 0);
    qkv_split_kernel<<<(NBH * 512 * 32) / 256, 256>>>(p_qkv);
    gemm_tf32<<<dim3(8, 8, NBH), 128>>>(512, 512, 32, p_Qh, p_Kt, nullptr,
                                        nullptr, nullptr, p_sc,
                                        512 * 32, 32 * 512, 512 * 512, ascale, 0);
    softmax_rows<<<NBH * 512 / 8, 256>>>(p_sc, 512);
    gemm_tf32<<<dim3(1, 8, NBH), 128>>>(512, 64, 512, p_sc, p_Vh, nullptr,
                                        nullptr, nullptr, p_Oh,
                                        512 * 512, 512 * 64, 512 * 64, 1.f, 0);
    o_merge_kernel<<<(BB * 512 * 256) / 256, 256>>>(p_o);
    gemm_tf32<<<dim3(4, 64, 1), 128>>>(4096, 256, 256, p_o, attn_w2, attn_b2,
                                       nullptr, nullptr, p_attn, 0, 0, 0, 1.f, 2);

    // ---- res block 2 ----
    gn_gelu_add<<<BB * GG, 256>>>(p_attn, emb, rb2_g1s, rb2_g1b, p_t1);
    im2col_kernel<<<(768 * 4096) / 256, 256>>>(p_t1, p_col);
    gemm_tf32<<<dim3(64, 4, 1), 128>>>(256, 4096, 768, rb2_c1w, p_col, rb2_c1b,
                                       nullptr, nullptr, p_t2, 0, 0, 0, 1.f, 1);
    gn_gelu_add<<<BB * GG, 256>>>(p_t2, nullptr, rb2_g2s, rb2_g2b, p_t3);
    im2col_kernel<<<(768 * 4096) / 256, 256>>>(p_t3, p_col);
    gemm_tf32<<<dim3(64, 4, 1), 128>>>(256, 4096, 768, rb2_c2w, p_col, rb2_c2b,
                                       p_attn, emb, p_x2, 0, 0, 0, 1.f, 1);

    // ---- MoE ----
    gemm_tf32<<<dim3(16, 32, 1), 128>>>(2048, 1024, 512, p_x2, moe_wg, nullptr,
                                        nullptr, nullptr, p_probs, 0, 0, 0, 1.f, 0);
    softmax_rows<<<NTOK / 8, 256>>>(p_probs, 1024);
    top2_kernel<<<NTOK, 256>>>(p_probs);
    colsum_kernel<<<BB * 4, 256>>>(p_probs);
    cudaMemsetAsync(p_ecount, 0, EE * sizeof(int));
    routing_par<<<BB, 256>>>();
    loss_kernel<<<1, 256>>>(aux_out);
    expert_kernel<<<EE, 256, expert_smem>>>(p_x2, moe_w1, moe_w2);
    combine_kernel<<<NTOK, 128>>>(x_out);

    // ---- final conv + maxpool ----
    im2col_kernel<<<(768 * 4096) / 256, 256>>>(x_out, p_col);
    gemm_tf32<<<dim3(64, 8, 1), 128>>>(512, 4096, 768, out_w, p_col, out_b,
                                       nullptr, nullptr, p_yfull, 0, 0, 0, 1.f, 1);
    maxpool_kernel<<<(Ysize + 255) / 256, 256>>>(p_yfull, y_out);
}

// round 16
// speedup vs baseline: 2.0579x; 1.0142x over previous
#include <cuda_runtime.h>
#include <math.h>
#include <stdint.h>

// Problem constants
#define BB   8
#define CC   256
#define LL   512
#define GG   32
#define HH   8
#define DH   32
#define EE   1024
#define HIDD 32
#define CAPX 4
#define NTOK (BB*CC)     // 2048 tokens
#define NBH  (BB*HH)     // 64 attention batches

// ---------------- scratch ----------------
__device__ float g_t1  [BB*CC*LL];
__device__ float g_t2  [BB*CC*LL];
__device__ float g_t3  [BB*CC*LL];
__device__ float g_s1  [BB*CC*LL];
__device__ float g_xt  [BB*LL*CC];
__device__ float g_qkv [BB*LL*3*CC];
__device__ float g_o   [BB*LL*CC];
__device__ float g_attn[BB*CC*LL];
__device__ float g_x2  [BB*CC*LL];
__device__ float g_col [768*4096];
__device__ float g_Qh  [NBH*512*32];
__device__ float g_Kt  [NBH*32*512];
__device__ float g_Vh  [NBH*512*64];
__device__ float g_Oh  [NBH*512*64];
__device__ float g_scores[NBH*512*512];
__device__ float g_probs[NTOK*EE];
__device__ float g_rawsum[BB*EE];
__device__ float g_cntf [BB*EE];
__device__ float g_v1[NTOK];  __device__ int g_i1[NTOK];
__device__ float g_v2[NTOK];  __device__ int g_i2[NTOK];
__device__ float g_g1[NTOK];  __device__ float g_g2[NTOK];
__device__ int   g_slot1[NTOK]; __device__ int g_slot2[NTOK];
__device__ int   g_ecount[EE];
__device__ int   g_etok[EE*32];
__device__ float g_eout[EE*32*512];
__device__ float g_yfull[BB*2*CC*LL];

__device__ __forceinline__ float gelu_exact(float v) {
    return 0.5f * v * (1.0f + erff(v * 0.70710678118654752440f));
}
__device__ __forceinline__ unsigned f2tf(float x) {
    unsigned r; asm("cvt.rna.tf32.f32 %0, %1;" : "=r"(r) : "f"(x)); return r;
}

// ---------------- fused (x [+ emb]) -> GroupNorm -> GELU ----------------
__global__ void gn_gelu_add(const float* __restrict__ in,
                            const float* __restrict__ in2,
                            const float* __restrict__ scale,
                            const float* __restrict__ bias,
                            float* __restrict__ out) {
    int bg = blockIdx.x;
    int b = bg >> 5, g = bg & 31;
    size_t off = ((size_t)b * CC + g * 8) * LL;
    const float4* base  = (const float4*)(in + off);
    const float4* base2 = in2 ? (const float4*)(in2 + off) : nullptr;
    float4* obase = (float4*)(out + off);
    __shared__ float rs[256], rq[256];
    int tid = threadIdx.x;
    float4 v[4];
    float s = 0.f, q = 0.f;
#pragma unroll
    for (int i = 0; i < 4; i++) {
        int idx = i * 256 + tid;
        float4 a = base[idx];
        if (base2) { float4 e = base2[idx]; a.x += e.x; a.y += e.y; a.z += e.z; a.w += e.w; }
        v[i] = a;
        s += a.x + a.y + a.z + a.w;
        q += a.x * a.x + a.y * a.y + a.z * a.z + a.w * a.w;
    }
    rs[tid] = s; rq[tid] = q;
    __syncthreads();
    for (int st = 128; st > 0; st >>= 1) {
        if (tid < st) { rs[tid] += rs[tid + st]; rq[tid] += rq[tid + st]; }
        __syncthreads();
    }
    float mu  = rs[0] * (1.f / 4096.f);
    float var = rq[0] * (1.f / 4096.f) - mu * mu;
    float inv = rsqrtf(var + 1e-5f);
#pragma unroll
    for (int i = 0; i < 4; i++) {
        int idx = i * 256 + tid;
        int c = g * 8 + (idx >> 7);
        float sc = scale[c] * inv, bi = bias[c] - mu * sc;
        float4 a = v[i];
        a.x = gelu_exact(a.x * sc + bi);
        a.y = gelu_exact(a.y * sc + bi);
        a.z = gelu_exact(a.z * sc + bi);
        a.w = gelu_exact(a.w * sc + bi);
        obase[idx] = a;
    }
}

// ---------------- im2col for k=3 pad=1 conv ----------------
__global__ void im2col_kernel(const float* __restrict__ in, float* __restrict__ col) {
    int idx = blockIdx.x * blockDim.x + threadIdx.x;
    if (idx >= 768 * 4096) return;
    int row = idx >> 12;
    int c4  = idx & 4095;
    int ci = row / 3, k = row % 3;
    int b = c4 >> 9, l = c4 & 511;
    int li = l + k - 1;
    float v = (li >= 0 && li < LL) ? in[((size_t)b * CC + ci) * LL + li] : 0.f;
    col[idx] = v;
}

// ---------------- tf32x3 tensor-core GEMM, register-pipelined ----------------
__global__ void __launch_bounds__(128) gemm_tf32(
    int M, int N, int K,
    const float* __restrict__ A, const float* __restrict__ B,
    const float* __restrict__ bias,
    const float* __restrict__ res1, const float* __restrict__ res2,
    float* __restrict__ C,
    long long sA, long long sB, long long sC,
    float alpha, int mode)
{
    __shared__ unsigned Ah[32 * 73];
    __shared__ unsigned Al[32 * 73];
    __shared__ unsigned Bh[32 * 72];
    __shared__ unsigned Bl[32 * 72];
    int tid = threadIdx.x;
    int z = blockIdx.z;
    const float* Ab = A + (size_t)z * sA;
    const float* Bb = B + (size_t)z * sB;
    int rowBase = blockIdx.y * 64;
    int colBase = blockIdx.x * 64;

    int lane = tid & 31, warp = tid >> 5;
    int wm = (warp & 1) * 32, wn = (warp >> 1) * 32;
    int grp = lane >> 2, tg = lane & 3;

    float acc[2][4][4];
#pragma unroll
    for (int mi = 0; mi < 2; mi++)
#pragma unroll
        for (int ni = 0; ni < 4; ni++)
#pragma unroll
            for (int r = 0; r < 4; r++) acc[mi][ni][r] = 0.f;

    int af = tid & 7, ar = tid >> 3;
    int bc = tid & 15, bk = tid >> 4;

    float4 pa[4], pb[4];
#pragma unroll
    for (int i = 0; i < 4; i++)
        pa[i] = *(const float4*)(Ab + (size_t)(rowBase + ar + i * 16) * K + af * 4);
#pragma unroll
    for (int i = 0; i < 4; i++)
        pb[i] = *(const float4*)(Bb + (size_t)(bk + i * 8) * N + colBase + bc * 4);

    for (int kb = 0; kb < K; kb += 32) {
#pragma unroll
        for (int i = 0; i < 4; i++) {
            int row = ar + i * 16;
            float f[4] = { pa[i].x, pa[i].y, pa[i].z, pa[i].w };
#pragma unroll
            for (int c = 0; c < 4; c++) {
                unsigned h = f2tf(f[c]);
                Ah[(af * 4 + c) * 73 + row] = h;
                Al[(af * 4 + c) * 73 + row] = f2tf(f[c] - __uint_as_float(h));
            }
        }
#pragma unroll
        for (int i = 0; i < 4; i++) {
            int k = bk + i * 8;
            float f[4] = { pb[i].x, pb[i].y, pb[i].z, pb[i].w };
#pragma unroll
            for (int c = 0; c < 4; c++) {
                unsigned h = f2tf(f[c]);
                Bh[k * 72 + bc * 4 + c] = h;
                Bl[k * 72 + bc * 4 + c] = f2tf(f[c] - __uint_as_float(h));
            }
        }
        __syncthreads();

        int kn = kb + 32;
        if (kn < K) {
#pragma unroll
            for (int i = 0; i < 4; i++)
                pa[i] = *(const float4*)(Ab + (size_t)(rowBase + ar + i * 16) * K + kn + af * 4);
#pragma unroll
            for (int i = 0; i < 4; i++)
                pb[i] = *(const float4*)(Bb + (size_t)(kn + bk + i * 8) * N + colBase + bc * 4);
        }

#pragma unroll
        for (int ks = 0; ks < 4; ks++) {
            int k0 = ks * 8;
            unsigned ah[2][4], al[2][4], bh[4][2], bl[4][2];
#pragma unroll
            for (int mi = 0; mi < 2; mi++) {
                int m = wm + mi * 16 + grp;
                ah[mi][0] = Ah[(k0 + tg) * 73 + m];
                ah[mi][1] = Ah[(k0 + tg) * 73 + m + 8];
                ah[mi][2] = Ah[(k0 + tg + 4) * 73 + m];
                ah[mi][3] = Ah[(k0 + tg + 4) * 73 + m + 8];
                al[mi][0] = Al[(k0 + tg) * 73 + m];
                al[mi][1] = Al[(k0 + tg) * 73 + m + 8];
                al[mi][2] = Al[(k0 + tg + 4) * 73 + m];
                al[mi][3] = Al[(k0 + tg + 4) * 73 + m + 8];
            }
#pragma unroll
            for (int ni = 0; ni < 4; ni++) {
                int n = wn + ni * 8 + grp;
                bh[ni][0] = Bh[(k0 + tg) * 72 + n];
                bh[ni][1] = Bh[(k0 + tg + 4) * 72 + n];
                bl[ni][0] = Bl[(k0 + tg) * 72 + n];
                bl[ni][1] = Bl[(k0 + tg + 4) * 72 + n];
            }
#pragma unroll
            for (int mi = 0; mi < 2; mi++)
#pragma unroll
                for (int ni = 0; ni < 4; ni++) {
                    float* d = acc[mi][ni];
                    asm volatile(
                        "mma.sync.aligned.m16n8k8.row.col.f32.tf32.tf32.f32 "
                        "{%0,%1,%2,%3},{%4,%5,%6,%7},{%8,%9},{%0,%1,%2,%3};"
                        : "+f"(d[0]), "+f"(d[1]), "+f"(d[2]), "+f"(d[3])
                        : "r"(ah[mi][0]), "r"(ah[mi][1]), "r"(ah[mi][2]), "r"(ah[mi][3]),
                          "r"(bl[ni][0]), "r"(bl[ni][1]));
                    asm volatile(
                        "mma.sync.aligned.m16n8k8.row.col.f32.tf32.tf32.f32 "
                        "{%0,%1,%2,%3},{%4,%5,%6,%7},{%8,%9},{%0,%1,%2,%3};"
                        : "+f"(d[0]), "+f"(d[1]), "+f"(d[2]), "+f"(d[3])
                        : "r"(al[mi][0]), "r"(al[mi][1]), "r"(al[mi][2]), "r"(al[mi][3]),
                          "r"(bh[ni][0]), "r"(bh[ni][1]));
                    asm volatile(
                        "mma.sync.aligned.m16n8k8.row.col.f32.tf32.tf32.f32 "
                        "{%0,%1,%2,%3},{%4,%5,%6,%7},{%8,%9},{%0,%1,%2,%3};"
                        : "+f"(d[0]), "+f"(d[1]), "+f"(d[2]), "+f"(d[3])
                        : "r"(ah[mi][0]), "r"(ah[mi][1]), "r"(ah[mi][2]), "r"(ah[mi][3]),
                          "r"(bh[ni][0]), "r"(bh[ni][1]));
                }
        }
        __syncthreads();
    }

    float* Cb = C + (size_t)z * sC;
#pragma unroll
    for (int mi = 0; mi < 2; mi++) {
#pragma unroll
        for (int ni = 0; ni < 4; ni++) {
#pragma unroll
            for (int r = 0; r < 4; r++) {
                int row = rowBase + wm + mi * 16 + grp + ((r >= 2) ? 8 : 0);
                int col = colBase + wn + ni * 8 + tg * 2 + (r & 1);
                float v = acc[mi][ni][r] * alpha;
                if (mode == 0) {
                    if (bias) v += bias[col];
                    Cb[(size_t)row * N + col] = v;
                } else if (mode == 1) {
                    int b = col >> 9, l = col & 511;
                    size_t oi = ((size_t)b * M + row) * LL + l;
                    if (bias) v += bias[row];
                    if (res1) v += res1[oi];
                    if (res2) v += res2[oi];
                    Cb[oi] = v;
                } else {
                    int b = row >> 9, l = row & 511;
                    size_t oi = ((size_t)b * N + col) * LL + l;
                    if (bias) v += bias[col];
                    Cb[oi] = v;
                }
            }
        }
    }
}

// ---------------- transpose (b,C,L) -> (b*L, C) ----------------
__global__ void transpose_kernel(const float* __restrict__ in, float* __restrict__ out) {
    __shared__ float tile[32][33];
    int b = blockIdx.z;
    int c0 = blockIdx.y * 32, l0 = blockIdx.x * 32;
    int tx = threadIdx.x, ty = threadIdx.y;
#pragma unroll
    for (int r = 0; r < 32; r += 8)
        tile[ty + r][tx] = in[((size_t)b * CC + c0 + ty + r) * LL + l0 + tx];
    __syncthreads();
#pragma unroll
    for (int r = 0; r < 32; r += 8)
        out[((size_t)b * LL + l0 + ty + r) * CC + c0 + tx] = tile[tx][ty + r];
}

// ---------------- qkv split ----------------
__global__ void qkv_split_kernel(const float* __restrict__ qkv) {
    int i = blockIdx.x * blockDim.x + threadIdx.x;
    if (i < NBH * 512 * 32) {
        int d = i & 31, l = (i >> 5) & 511, bh = i >> 14;
        int b = bh >> 3, h = bh & 7;
        const float* src = qkv + ((size_t)(b * 512 + l) * 768) + (d * 8 + h) * 3;
        g_Qh[(size_t)bh * 16384 + l * 32 + d] = src[0];
        g_Vh[(size_t)bh * 32768 + l * 64 + d] = src[2];
        g_Vh[(size_t)bh * 32768 + l * 64 + 32 + d] = 0.f;
        int l2 = i & 511, d2 = (i >> 9) & 31, bh2 = i >> 14;
        int b2 = bh2 >> 3, h2 = bh2 & 7;
        g_Kt[(size_t)bh2 * 16384 + d2 * 512 + l2] =
            qkv[((size_t)(b2 * 512 + l2) * 768) + (d2 * 8 + h2) * 3 + 1];
    }
}

// ---------------- row softmax (warp per row) ----------------
__global__ void softmax_rows(float* __restrict__ p, int cols) {
    int row = blockIdx.x * 8 + (threadIdx.x >> 5);
    int lane = threadIdx.x & 31;
    float4* r = (float4*)(p + (size_t)row * cols);
    int per = cols >> 7;
    float4 v[8];
    float m = -1e30f;
    for (int i = 0; i < per; i++) {
        v[i] = r[i * 32 + lane];
        m = fmaxf(m, fmaxf(fmaxf(v[i].x, v[i].y), fmaxf(v[i].z, v[i].w)));
    }
#pragma unroll
    for (int off = 16; off > 0; off >>= 1) m = fmaxf(m, __shfl_xor_sync(0xffffffffu, m, off));
    float s = 0.f;
    for (int i = 0; i < per; i++) {
        v[i].x = expf(v[i].x - m); v[i].y = expf(v[i].y - m);
        v[i].z = expf(v[i].z - m); v[i].w = expf(v[i].w - m);
        s += v[i].x + v[i].y + v[i].z + v[i].w;
    }
#pragma unroll
    for (int off = 16; off > 0; off >>= 1) s += __shfl_xor_sync(0xffffffffu, s, off);
    float inv = 1.f / s;
    for (int i = 0; i < per; i++) {
        v[i].x *= inv; v[i].y *= inv; v[i].z *= inv; v[i].w *= inv;
        r[i * 32 + lane] = v[i];
    }
}

// ---------------- merge heads ----------------
__global__ void o_merge_kernel(float* __restrict__ o) {
    int i = blockIdx.x * blockDim.x + threadIdx.x;
    if (i >= BB * 512 * 256) return;
    int c = i & 255, l = (i >> 8) & 511, b = i >> 17;
    int h = c & 7, d = c >> 3;
    o[i] = g_Oh[(size_t)(b * 8 + h) * 32768 + l * 64 + d];
}

// ---------------- top-2 (first-occurrence tie-break) ----------------
__global__ void top2_kernel(const float* __restrict__ probs) {
    int row = blockIdx.x;
    const float* p = probs + (size_t)row * EE;
    __shared__ float sv[256]; __shared__ int si[256];
    int tid = threadIdx.x;
    float bv = -1e30f; int bi = 0;
    for (int e = tid * 4; e < tid * 4 + 4; e++) { float v = p[e]; if (v > bv) { bv = v; bi = e; } }
    sv[tid] = bv; si[tid] = bi; __syncthreads();
    for (int st = 128; st > 0; st >>= 1) {
        if (tid < st) {
            if (sv[tid + st] > sv[tid] || (sv[tid + st] == sv[tid] && si[tid + st] < si[tid])) {
                sv[tid] = sv[tid + st]; si[tid] = si[tid + st];
            }
        }
        __syncthreads();
    }
    float v1 = sv[0]; int i1 = si[0];
    __syncthreads();
    bv = -1e30f; bi = 0;
    for (int e = tid * 4; e < tid * 4 + 4; e++) {
        if (e == i1) continue;
        float v = p[e]; if (v > bv) { bv = v; bi = e; }
    }
    sv[tid] = bv; si[tid] = bi; __syncthreads();
    for (int st = 128; st > 0; st >>= 1) {
        if (tid < st) {
            if (sv[tid + st] > sv[tid] || (sv[tid + st] == sv[tid] && si[tid + st] < si[tid])) {
                sv[tid] = sv[tid + st]; si[tid] = si[tid + st];
            }
        }
        __syncthreads();
    }
    if (tid == 0) { g_v1[row] = v1; g_i1[row] = i1; g_v2[row] = sv[0]; g_i2[row] = si[0]; }
}

// ---------------- per-(b,e) raw prob sums ----------------
__global__ void colsum_kernel(const float* __restrict__ probs) {
    int b = blockIdx.x >> 2;
    int e = ((blockIdx.x & 3) << 8) + threadIdx.x;
    float s = 0.f;
    for (int n = 0; n < CC; n++) s += probs[((size_t)(b * CC + n)) * EE + e];
    g_rawsum[b * EE + e] = s;
}

// ---------------- parallel capacity routing ----------------
__global__ void routing_par() {
    __shared__ int si1[256], si2[256];
    __shared__ int scnt[EE];
    int b = blockIdx.x;
    int tid = threadIdx.x;
    int t = b * 256 + tid;
    si1[tid] = g_i1[t]; si2[tid] = g_i2[t];
    for (int e = tid; e < EE; e += 256) scnt[e] = 0;
    __syncthreads();
    atomicAdd(&scnt[si1[tid]], 1);
    int e1 = si1[tid], e2 = si2[tid];
    int pos1 = 0, cnt_e2 = 0;
    for (int m = 0; m < 256; m++) {
        int v = si1[m];
        pos1   += (v == e1 && m < tid);
        cnt_e2 += (v == e2);
    }
    float v1 = g_v1[t], v2 = g_v2[t];
    float denom = v1 + v2 + 1e-9f;
    float g1 = (pos1 < CAPX) ? (v1 / denom) : 0.f;
    int pos2 = min(cnt_e2, CAPX);
    for (int m = 0; m < 256; m++) {
        pos2 += (si2[m] == e2 && m < tid);
    }
    float g2 = (pos2 < CAPX) ? (v2 / denom) : 0.f;
    g_g1[t] = g1; g_g2[t] = g2;
    int s1 = 0, s2 = 0;
    if (g1 > 0.f) { s1 = atomicAdd(&g_ecount[e1], 1); g_etok[e1 * 32 + s1] = t; }
    if (g2 > 0.f) { s2 = atomicAdd(&g_ecount[e2], 1); g_etok[e2 * 32 + s2] = t; }
    g_slot1[t] = s1; g_slot2[t] = s2;
    __syncthreads();
    for (int e = tid; e < EE; e += 256) g_cntf[b * EE + e] = (float)scnt[e];
}

// ---------------- aux loss ----------------
__global__ void loss_kernel(float* __restrict__ out_aux) {
    __shared__ float red[256];
    int tid = threadIdx.x;
    float s = 0.f;
    for (int i = tid; i < BB * EE; i += 256) s += g_rawsum[i] * g_cntf[i];
    red[tid] = s; __syncthreads();
    for (int st = 128; st > 0; st >>= 1) { if (tid < st) red[tid] += red[tid + st]; __syncthreads(); }
    if (tid == 0) {
        float S = red[0];
        float loss = (S / ((float)CC * (float)CC)) / ((float)BB * (float)EE)
                     * (float)EE * (float)EE * 0.01f;
        *out_aux = loss;
    }
}

// ---------------- expert MLP ----------------
__global__ void __launch_bounds__(256) expert_kernel(const float* __restrict__ x,
                                                     const float* __restrict__ w1,
                                                     const float* __restrict__ w2) {
    int e = blockIdx.x;
    int cnt = g_ecount[e];
    if (cnt == 0) return;
    extern __shared__ float sm[];
    float* W1s = sm;             // [512][33]
    float* W2s = sm + 512 * 33;  // [32][512]
    float* hs  = W2s + 32 * 512; // [32 tok][32]
    int tid = threadIdx.x;
    const float* w1e = w1 + (size_t)e * 512 * 32;
    const float* w2e = w2 + (size_t)e * 32 * 512;
    for (int i = tid; i < 512 * 32; i += 256) {
        W1s[(i >> 5) * 33 + (i & 31)] = w1e[i];
        W2s[i] = w2e[i];
    }
    __syncthreads();
    int warp = tid >> 5, lane = tid & 31;
    for (int t0 = warp; t0 < cnt; t0 += 8) {
        int tok = g_etok[e * 32 + t0];
        const float* xr = x + (size_t)tok * 512;
        float xv[16];
#pragma unroll
        for (int i = 0; i < 16; i++) xv[i] = xr[lane + 32 * i];
#pragma unroll
        for (int j = 0; j < 32; j++) {
            float s = 0.f;
#pragma unroll
            for (int i = 0; i < 16; i++) s += xv[i] * W1s[(lane + 32 * i) * 33 + j];
#pragma unroll
            for (int off = 16; off > 0; off >>= 1) s += __shfl_xor_sync(0xffffffffu, s, off);
            if (lane == 0) hs[t0 * 32 + j] = gelu_exact(s);
        }
        __syncwarp();
        float hv[32];
#pragma unroll
        for (int j = 0; j < 32; j++) hv[j] = hs[t0 * 32 + j];
#pragma unroll
        for (int i = 0; i < 16; i++) {
            int d = lane + 32 * i;
            float s = 0.f;
#pragma unroll
            for (int j = 0; j < 32; j++) s += hv[j] * W2s[j * 512 + d];
            g_eout[((size_t)e * 32 + t0) * 512 + d] = s;
        }
    }
}

// ---------------- combine expert outputs ----------------
__global__ void combine_kernel(float* __restrict__ out) {
    int t = blockIdx.x;
    int tid = threadIdx.x;
    float g1 = g_g1[t], g2 = g_g2[t];
    float4 v = make_float4(0.f, 0.f, 0.f, 0.f);
    if (g1 > 0.f) {
        const float4* p = (const float4*)(g_eout + ((size_t)g_i1[t] * 32 + g_slot1[t]) * 512);
        float4 a = p[tid];
        v.x += g1 * a.x; v.y += g1 * a.y; v.z += g1 * a.z; v.w += g1 * a.w;
    }
    if (g2 > 0.f) {
        const float4* p = (const float4*)(g_eout + ((size_t)g_i2[t] * 32 + g_slot2[t]) * 512);
        float4 a = p[tid];
        v.x += g2 * a.x; v.y += g2 * a.y; v.z += g2 * a.z; v.w += g2 * a.w;
    }
    ((float4*)(out + (size_t)t * 512))[tid] = v;
}

// ---------------- maxpool w=3 s=2 p=1 ----------------
__global__ void maxpool_kernel(const float* __restrict__ y, float* __restrict__ out) {
    int idx = blockIdx.x * blockDim.x + threadIdx.x;
    if (idx >= BB * 2 * CC * 256) return;
    int lp = idx & 255;
    int co = (idx >> 8) & 511;
    int b = idx >> 17;
    int l = lp * 2;
    float m = -INFINITY;
#pragma unroll
    for (int k = -1; k <= 1; k++) {
        int li = l + k;
        if (li >= 0 && li < LL) m = fmaxf(m, y[((size_t)b * 512 + co) * LL + li]);
    }
    out[idx] = m;
}

// ---------------- host ----------------
static float* sym(const void* s) { void* p = nullptr; cudaGetSymbolAddress(&p, s); return (float*)p; }

extern "C" void kernel_launch(void* const* d_in, const int* in_sizes, int n_in,
                              void* d_out, int out_size) {
    const float* x_in   = (const float*)d_in[0];
    const float* emb    = (const float*)d_in[1];
    const float* rb1_g1s = (const float*)d_in[2];
    const float* rb1_g1b = (const float*)d_in[3];
    const float* rb1_c1w = (const float*)d_in[4];
    const float* rb1_c1b = (const float*)d_in[5];
    const float* rb1_g2s = (const float*)d_in[6];
    const float* rb1_g2b = (const float*)d_in[7];
    const float* rb1_c2w = (const float*)d_in[8];
    const float* rb1_c2b = (const float*)d_in[9];
    const float* rb2_g1s = (const float*)d_in[10];
    const float* rb2_g1b = (const float*)d_in[11];
    const float* rb2_c1w = (const float*)d_in[12];
    const float* rb2_c1b = (const float*)d_in[13];
    const float* rb2_g2s = (const float*)d_in[14];
    const float* rb2_g2b = (const float*)d_in[15];
    const float* rb2_c2w = (const float*)d_in[16];
    const float* rb2_c2b = (const float*)d_in[17];
    const float* attn_w1 = (const float*)d_in[18];
    const float* attn_b1 = (const float*)d_in[19];
    const float* attn_w2 = (const float*)d_in[20];
    const float* attn_b2 = (const float*)d_in[21];
    const float* moe_wg  = (const float*)d_in[22];
    const float* moe_w1  = (const float*)d_in[23];
    const float* moe_w2  = (const float*)d_in[24];
    const float* out_w   = (const float*)d_in[25];
    const float* out_b   = (const float*)d_in[26];

    float* out = (float*)d_out;
    const int Ysize = BB * 2 * CC * 256;
    float* y_out = out;
    float* x_out = out + Ysize;
    float* aux_out = out + (out_size - 1);

    float* p_t1 = sym(g_t1); float* p_t2 = sym(g_t2); float* p_t3 = sym(g_t3);
    float* p_s1 = sym(g_s1); float* p_xt = sym(g_xt); float* p_qkv = sym(g_qkv);
    float* p_o = sym(g_o);  float* p_attn = sym(g_attn); float* p_x2 = sym(g_x2);
    float* p_col = sym(g_col); float* p_probs = sym(g_probs); float* p_yfull = sym(g_yfull);
    float* p_Qh = sym(g_Qh); float* p_Kt = sym(g_Kt); float* p_Vh = sym(g_Vh);
    float* p_Oh = sym(g_Oh); float* p_sc = sym(g_scores);
    void* p_ecount = nullptr; cudaGetSymbolAddress(&p_ecount, g_ecount);

    const int expert_smem = (512 * 33 + 32 * 512 + 32 * 32) * 4;
    cudaFuncSetAttribute(expert_kernel, cudaFuncAttributeMaxDynamicSharedMemorySize, expert_smem);

    const float ascale = 0.17677669529663687f;  // 1/sqrt(32)

    // ---- res block 1 ----
    gn_gelu_add<<<BB * GG, 256>>>(x_in, emb, rb1_g1s, rb1_g1b, p_t1);
    im2col_kernel<<<(768 * 4096) / 256, 256>>>(p_t1, p_col);
    gemm_tf32<<<dim3(64, 4, 1), 128>>>(256, 4096, 768, rb1_c1w, p_col, rb1_c1b,
                                       nullptr, nullptr, p_t2, 0, 0, 0, 1.f, 1);
    gn_gelu_add<<<BB * GG, 256>>>(p_t2, nullptr, rb1_g2s, rb1_g2b, p_t3);
    im2col_kernel<<<(768 * 4096) / 256, 256>>>(p_t3, p_col);
    gemm_tf32<<<dim3(64, 4, 1), 128>>>(256, 4096, 768, rb1_c2w, p_col, rb1_c2b,
                                       x_in, emb, p_s1, 0, 0, 0, 1.f, 1);

    // ---- attention ----
    transpose_kernel<<<dim3(16, 8, BB), dim3(32, 8)>>>(p_s1, p_xt);
    gemm_tf32<<<dim3(12, 64, 1), 128>>>(4096, 768, 256, p_xt, attn_w1, attn_b1,
                                        nullptr, nullptr, p_qkv, 0, 0, 0, 1.f, 0);
    qkv_split_kernel<<<(NBH * 512 * 32) / 256, 256>>>(p_qkv);
    gemm_tf32<<<dim3(8, 8, NBH), 128>>>(512, 512, 32, p_Qh, p_Kt, nullptr,
                                        nullptr, nullptr, p_sc,
                                        512 * 32, 32 * 512, 512 * 512, ascale, 0);
    softmax_rows<<<NBH * 512 / 8, 256>>>(p_sc, 512);
    gemm_tf32<<<dim3(1, 8, NBH), 128>>>(512, 64, 512, p_sc, p_Vh, nullptr,
                                        nullptr, nullptr, p_Oh,
                                        512 * 512, 512 * 64, 512 * 64, 1.f, 0);
    o_merge_kernel<<<(BB * 512 * 256) / 256, 256>>>(p_o);
    gemm_tf32<<<dim3(4, 64, 1), 128>>>(4096, 256, 256, p_o, attn_w2, attn_b2,
                                       nullptr, nullptr, p_attn, 0, 0, 0, 1.f, 2);

    // ---- res block 2 ----
    gn_gelu_add<<<BB * GG, 256>>>(p_attn, emb, rb2_g1s, rb2_g1b, p_t1);
    im2col_kernel<<<(768 * 4096) / 256, 256>>>(p_t1, p_col);
    gemm_tf32<<<dim3(64, 4, 1), 128>>>(256, 4096, 768, rb2_c1w, p_col, rb2_c1b,
                                       nullptr, nullptr, p_t2, 0, 0, 0, 1.f, 1);
    gn_gelu_add<<<BB * GG, 256>>>(p_t2, nullptr, rb2_g2s, rb2_g2b, p_t3);
    im2col_kernel<<<(768 * 4096) / 256, 256>>>(p_t3, p_col);
    gemm_tf32<<<dim3(64, 4, 1), 128>>>(256, 4096, 768, rb2_c2w, p_col, rb2_c2b,
                                       p_attn, emb, p_x2, 0, 0, 0, 1.f, 1);

    // ---- MoE ----
    gemm_tf32<<<dim3(16, 32, 1), 128>>>(2048, 1024, 512, p_x2, moe_wg, nullptr,
                                        nullptr, nullptr, p_probs, 0, 0, 0, 1.f, 0);
    softmax_rows<<<NTOK / 8, 256>>>(p_probs, 1024);
    top2_kernel<<<NTOK, 256>>>(p_probs);
    colsum_kernel<<<BB * 4, 256>>>(p_probs);
    cudaMemsetAsync(p_ecount, 0, EE * sizeof(int));
    routing_par<<<BB, 256>>>();
    loss_kernel<<<1, 256>>>(aux_out);
    expert_kernel<<<EE, 256, expert_smem>>>(p_x2, moe_w1, moe_w2);
    combine_kernel<<<NTOK, 128>>>(x_out);

    // ---- final conv + maxpool ----
    im2col_kernel<<<(768 * 4096) / 256, 256>>>(x_out, p_col);
    gemm_tf32<<<dim3(64, 8, 1), 128>>>(512, 4096, 768, out_w, p_col, out_b,
                                       nullptr, nullptr, p_yfull, 0, 0, 0, 1.f, 1);
    maxpool_kernel<<<(Ysize + 255) / 256, 256>>>(p_yfull, y_out);
}